// round 12
// baseline (speedup 1.0000x reference)
#include <cuda_runtime.h>
#include <cuda_bf16.h>
#include <stdint.h>

#define NB 1024

// ---------------- scratch (no allocations allowed) ----------------
__device__ float g_maxabs[4];                           // zero-init; reset by fc2 tail
__device__ int   g_cnt2;                                // fc2 completion ticket
__device__ __align__(16) int8_t g_qx  [NB * 784];       // quantized input q
__device__ __align__(16) int8_t g_qw1 [32 * 9];         // [oc][kpos]
__device__ __align__(16) int8_t g_qw2 [64 * 9 * 32];    // [oc][kpos 9][ic 32] rows of 288
__device__ __align__(16) int8_t g_act2[NB * 832];       // fc1 A, s4-packed rows (800B data + 32B zero pad)
__device__ __align__(16) int8_t g_qwl1[4096 * 832];     // fc1 B, s4-packed rows (pad zero-init)
__device__ __align__(16) int8_t g_act3[NB * 4096];      // fc1 output q (0..15)
__device__ __align__(16) int8_t g_qwl2[10 * 4096];      // [n][k]

__device__ __forceinline__ int clampi(int v, int lo, int hi) {
    return max(lo, min(hi, v));
}
__device__ __forceinline__ int dp4(uint32_t a, uint32_t b, int c) {
    return __dp4a((int)a, (int)b, c);   // signed byte dot-product
}
__device__ __forceinline__ uint32_t smem_u32(const void* p) {
    return (uint32_t)__cvta_generic_to_shared(p);
}
__device__ __forceinline__ void ldsm4(uint32_t& r0, uint32_t& r1, uint32_t& r2,
                                      uint32_t& r3, uint32_t a) {
    asm volatile("ldmatrix.sync.aligned.m8n8.x4.shared.b16 {%0,%1,%2,%3}, [%4];\n"
                 : "=r"(r0), "=r"(r1), "=r"(r2), "=r"(r3) : "r"(a));
}
__device__ __forceinline__ void imma16832(int* c, const uint32_t* a, const uint32_t* b) {
    asm volatile(
        "mma.sync.aligned.m16n8k32.row.col.s32.s8.s8.s32 "
        "{%0,%1,%2,%3},{%4,%5,%6,%7},{%8,%9},{%0,%1,%2,%3};\n"
        : "+r"(c[0]), "+r"(c[1]), "+r"(c[2]), "+r"(c[3])
        : "r"(a[0]), "r"(a[1]), "r"(a[2]), "r"(a[3]), "r"(b[0]), "r"(b[1]));
}
// int4 MMA: K=64 per instruction; fragment bytes identical to s8 k32 layout.
__device__ __forceinline__ void imma16864s4(int* c, const uint32_t* a, const uint32_t* b) {
    asm volatile(
        "mma.sync.aligned.m16n8k64.row.col.s32.s4.s4.s32 "
        "{%0,%1,%2,%3},{%4,%5,%6,%7},{%8,%9},{%0,%1,%2,%3};\n"
        : "+r"(c[0]), "+r"(c[1]), "+r"(c[2]), "+r"(c[3])
        : "r"(a[0]), "r"(a[1]), "r"(a[2]), "r"(a[3]), "r"(b[0]), "r"(b[1]));
}
__device__ __forceinline__ uint32_t pack2n(int a, int b) {  // two s4 -> one byte
    return (uint32_t)(a & 0xF) | (((uint32_t)(b & 0xF)) << 4);
}
#define CPA16(dst, src) \
    asm volatile("cp.async.cg.shared.global [%0], [%1], 16;\n" ::"r"(dst), "l"(src))
#define CPC()  asm volatile("cp.async.commit_group;\n")
#define CPW0() asm volatile("cp.async.wait_group 0;\n")

// ---------------- maxabs (+ fused quant_x) ----------------
__device__ void maxabs_dev(const float* __restrict__ w, int n4, int idx,
                           int bid, int nblocks) {
    const float4* w4 = (const float4*)w;
    int G = nblocks * 256;
    int i0 = bid * 256 + threadIdx.x;
    float m0 = 0.f, m1 = 0.f, m2 = 0.f, m3 = 0.f;
    for (int i = i0; i < n4; i += 4 * G) {
        float4 v = w4[i];
        m0 = fmaxf(m0, fmaxf(fmaxf(fabsf(v.x), fabsf(v.y)),
                             fmaxf(fabsf(v.z), fabsf(v.w))));
        int i1 = i + G;
        if (i1 < n4) {
            float4 u = w4[i1];
            m1 = fmaxf(m1, fmaxf(fmaxf(fabsf(u.x), fabsf(u.y)),
                                 fmaxf(fabsf(u.z), fabsf(u.w))));
        }
        int i2 = i + 2 * G;
        if (i2 < n4) {
            float4 u = w4[i2];
            m2 = fmaxf(m2, fmaxf(fmaxf(fabsf(u.x), fabsf(u.y)),
                                 fmaxf(fabsf(u.z), fabsf(u.w))));
        }
        int i3 = i + 3 * G;
        if (i3 < n4) {
            float4 u = w4[i3];
            m3 = fmaxf(m3, fmaxf(fmaxf(fabsf(u.x), fabsf(u.y)),
                                 fmaxf(fabsf(u.z), fabsf(u.w))));
        }
    }
    float m = fmaxf(fmaxf(m0, m1), fmaxf(m2, m3));
    #pragma unroll
    for (int o = 16; o; o >>= 1) m = fmaxf(m, __shfl_xor_sync(0xffffffffu, m, o));
    __shared__ float sm[8];
    int lane = threadIdx.x & 31, wid = threadIdx.x >> 5;
    if (lane == 0) sm[wid] = m;
    __syncthreads();
    if (wid == 0) {
        m = (lane < 8) ? sm[lane] : 0.0f;
        #pragma unroll
        for (int o = 4; o; o >>= 1) m = fmaxf(m, __shfl_xor_sync(0xffffffffu, m, o));
        if (lane == 0) atomicMax((int*)&g_maxabs[idx], __float_as_int(m));
    }
}

// blocks: [0,1024) wl1 max, [1024,1042) w2, [1042,1082) wl2, [1082] w1,
//         [1083, 1475) quant_x (each thread covers 2 elements: i, i+100352)
__global__ void prep1_k(const float* __restrict__ w1,
                        const float* __restrict__ w2,
                        const float* __restrict__ wl1,
                        const float* __restrict__ wl2,
                        const float* __restrict__ x,
                        const float* __restrict__ s_in_p) {
    int bx = blockIdx.x;
    if (bx < 1024)        maxabs_dev(wl1, (4096 * 1600) >> 2, 2, bx, 1024);
    else if (bx < 1042)   maxabs_dev(w2, (64 * 32 * 9) >> 2, 1, bx - 1024, 18);
    else if (bx < 1082)   maxabs_dev(wl2, (10 * 4096) >> 2, 3, bx - 1042, 40);
    else if (bx == 1082)  maxabs_dev(w1, (32 * 9) >> 2, 0, 0, 1);
    else {
        float inv = 1.0f / *s_in_p;  // s_in power of two -> exact
        const int n4 = (NB * 784) >> 2;  // 200704
        const int half = 392 * 256;      // 100352
        const float4* x4 = (const float4*)x;
        char4* q4 = (char4*)g_qx;
        int i = (bx - 1083) * 256 + (int)threadIdx.x;
        #pragma unroll
        for (int rep = 0; rep < 2; rep++) {
            int ii = i + rep * half;
            if (ii < n4) {
                float4 v = x4[ii];
                char4 q;
                q.x = (char)clampi((int)rintf(v.x * inv), -8, 7);
                q.y = (char)clampi((int)rintf(v.y * inv), -8, 7);
                q.z = (char)clampi((int)rintf(v.z * inv), -8, 7);
                q.w = (char)clampi((int)rintf(v.w * inv), -8, 7);
                q4[ii] = q;
            }
        }
    }
}

// blocks: [0,2048) wl1 (s4 pack), [2048,2208) wl2, [2208,2280) w2, [2280,2282) w1
__global__ void quant_w_k(const float* __restrict__ w1,
                          const float* __restrict__ w2,
                          const float* __restrict__ wl1,
                          const float* __restrict__ wl2) {
    int bx = blockIdx.x, tid = threadIdx.x;
    if (bx < 2048) {
        float rinv = 1.0f / (g_maxabs[2] / 7.0f);
        const int nw = 4096 * 200;   // u32 words of packed output (8 floats -> 4B)
        for (int w = bx * 256 + tid; w < nw; w += 2048 * 256) {
            int n = w / 200, j = w - n * 200;
            const float4* src = (const float4*)(wl1 + (size_t)n * 1600 + j * 8);
            float4 v0 = src[0], v1 = src[1];
            int q0 = clampi((int)rintf(v0.x * rinv), -7, 7);
            int q1 = clampi((int)rintf(v0.y * rinv), -7, 7);
            int q2 = clampi((int)rintf(v0.z * rinv), -7, 7);
            int q3 = clampi((int)rintf(v0.w * rinv), -7, 7);
            int q4 = clampi((int)rintf(v1.x * rinv), -7, 7);
            int q5 = clampi((int)rintf(v1.y * rinv), -7, 7);
            int q6 = clampi((int)rintf(v1.z * rinv), -7, 7);
            int q7 = clampi((int)rintf(v1.w * rinv), -7, 7);
            uint32_t word = pack2n(q0, q1) | (pack2n(q2, q3) << 8)
                          | (pack2n(q4, q5) << 16) | (pack2n(q6, q7) << 24);
            *(uint32_t*)(g_qwl1 + (size_t)n * 832 + j * 4) = word;
        }
    } else if (bx < 2208) {
        float s = g_maxabs[3] / 7.0f;
        int i = (bx - 2048) * 256 + tid;
        if (i < 10 * 4096)
            g_qwl2[i] = (int8_t)clampi((int)rintf(wl2[i] / s), -7, 7);
    } else if (bx < 2280) {
        float s = g_maxabs[1] / 7.0f;
        int i = (bx - 2208) * 256 + tid;
        if (i < 64 * 9 * 32) {
            int oc = i / 288, r = i % 288;
            int pos = r >> 5, ic = r & 31;
            float v = w2[(oc * 32 + ic) * 9 + pos];
            g_qw2[i] = (int8_t)clampi((int)rintf(v / s), -7, 7);
        }
    } else {
        float s = g_maxabs[0] / 7.0f;
        int i = (bx - 2280) * 256 + tid;
        if (i < 32 * 9)
            g_qw1[i] = (int8_t)clampi((int)rintf(w1[i] / s), -7, 7);
    }
}

// ---------------- fused conv1+pool+fq  ->  conv2(IMMA)+pool+fq ----------------
// conv1: 169 threads, one pool pixel each (4x4 receptive field in regs), dp4a.
// Pool-before-quantize (monotone map) + reciprocal multiplies (scales are 2^k).
// Epilogue packs act2 rows to s4 nibbles for the int4 fc1.
#define A1S 48
#define WS2 304
__global__ __launch_bounds__(256) void conv12_k(const float* __restrict__ s_in_p,
                                                const float* __restrict__ s_a1_p,
                                                const float* __restrict__ s_a2_p) {
    __shared__ __align__(16) int8_t S[35072];
    int8_t* sw2 = S;                             // 64*304 = 19456
    int8_t* a1s = S + 19456;                     // act1 tile (stride 48), 8576
    int8_t* sx  = S + 28032;                     // 784
    uint32_t* swp = (uint32_t*)(S + 28832);      // packed conv1 weights, 96 u32
    int b = blockIdx.x, tid = threadIdx.x;
    int lane = tid & 31, wid = tid >> 5;

    for (int idx = tid; idx < 1152; idx += 256) {
        int row = idx / 18, seg = idx % 18;
        CPA16(smem_u32(sw2 + row * WS2 + seg * 16),
              (const char*)g_qw2 + row * 288 + seg * 16);
    }
    CPC();
    {
        const int* gx = (const int*)(g_qx + b * 784);
        int* sxi = (int*)sx;
        for (int i = tid; i < 196; i += 256) sxi[i] = gx[i];
        if (tid < 96) {  // pack w1[oc][ky][0..2] -> u32 with zero 4th byte
            int oc = tid / 3, ky = tid - oc * 3;
            const uint8_t* wp = (const uint8_t*)g_qw1 + oc * 9 + ky * 3;
            swp[tid] = (uint32_t)wp[0] | ((uint32_t)wp[1] << 8)
                     | ((uint32_t)wp[2] << 16);
        }
    }
    __syncthreads();

    float s_in = *s_in_p, s_a1 = *s_a1_p, s_a2 = *s_a2_p;
    float inv_in = 1.0f / s_in, inv_a1 = 1.0f / s_a1, inv_a2 = 1.0f / s_a2;
    float mul1 = s_in * (g_maxabs[0] / 7.0f);

    if (tid < 169) {
        int py = tid / 13, px = tid - py * 13;
        int c0 = 2 * px;
        uint32_t V[4];
        #pragma unroll
        for (int r = 0; r < 4; r++) {
            int boff = (2 * py + r) * 28 + c0;
            int b4 = boff & ~3;
            uint32_t lo = *(const uint32_t*)(sx + b4);
            if (boff & 2) {
                uint32_t hi = *(const uint32_t*)(sx + b4 + 4);
                V[r] = __funnelshift_r(lo, hi, 16);
            } else {
                V[r] = lo;
            }
        }
        uint32_t Q[4][2];
        #pragma unroll
        for (int r = 0; r < 4; r++) {
            Q[r][0] = V[r] & 0x00FFFFFFu;
            Q[r][1] = (V[r] >> 8) & 0x00FFFFFFu;
        }
        int8_t* arow = a1s + tid * A1S;
        #pragma unroll
        for (int g = 0; g < 8; g++) {
            uint32_t pk = 0;
            #pragma unroll
            for (int j = 0; j < 4; j++) {
                int oc = g * 4 + j;
                uint32_t w0 = swp[oc * 3 + 0], w1 = swp[oc * 3 + 1],
                         w2 = swp[oc * 3 + 2];
                int a00 = dp4(Q[0][0], w0, dp4(Q[1][0], w1, dp4(Q[2][0], w2, 0)));
                int a01 = dp4(Q[0][1], w0, dp4(Q[1][1], w1, dp4(Q[2][1], w2, 0)));
                int a10 = dp4(Q[1][0], w0, dp4(Q[2][0], w1, dp4(Q[3][0], w2, 0)));
                int a11 = dp4(Q[1][1], w0, dp4(Q[2][1], w1, dp4(Q[3][1], w2, 0)));
                int m = max(max(a00, a01), max(a10, a11));
                float v = (float)m * mul1;
                int q = clampi((int)rintf(v * inv_a1), 0, 15);
                float v2 = (float)q * s_a1;
                int q2 = clampi((int)rintf(v2 * inv_in), -8, 7);
                pk |= ((uint32_t)q2 & 0xFFu) << (j * 8);
            }
            *(uint32_t*)(arow + g * 4) = pk;
        }
    }
    CPW0();
    __syncthreads();

    // conv2 IMMA: A[128 conv-pix][288] gathered from a1s, B = sw2 [64 oc][288]
    int wm = wid >> 1, wn = wid & 1;
    int c[2][4][4];
    #pragma unroll
    for (int h = 0; h < 2; h++)
        #pragma unroll
        for (int nt = 0; nt < 4; nt++)
            #pragma unroll
            for (int e = 0; e < 4; e++) c[h][nt][e] = 0;

    uint32_t bbase = smem_u32(sw2)
                   + (wn * 32 + (lane & 7) + ((lane >> 4) << 3)) * WS2
                   + (((lane >> 3) & 1) << 4);
    uint32_t abase_h[2];
    {
        int khalf = lane >> 4;
        #pragma unroll
        for (int h = 0; h < 2; h++) {
            int p = h * 64 + wm * 16 + (lane & 15);
            int cy = p / 11, cx = p % 11;
            abase_h[h] = smem_u32(a1s) + (cy * 13 + cx) * A1S + khalf * 16;
        }
    }

    #pragma unroll
    for (int h = 0; h < 2; h++) {
        #pragma unroll
        for (int ks = 0; ks < 9; ks++) {
            int ky = ks / 3, kx = ks % 3;
            uint32_t a[4];
            ldsm4(a[0], a[1], a[2], a[3], abase_h[h] + (ky * 13 + kx) * A1S);
            uint32_t bb[4][2];
            #pragma unroll
            for (int j = 0; j < 2; j++) {
                uint32_t r0, r1, r2, r3;
                ldsm4(r0, r1, r2, r3, bbase + j * 16 * WS2 + ks * 32);
                bb[2 * j][0] = r0;     bb[2 * j][1] = r1;
                bb[2 * j + 1][0] = r2; bb[2 * j + 1][1] = r3;
            }
            #pragma unroll
            for (int nt = 0; nt < 4; nt++)
                imma16832(c[h][nt], a, bb[nt]);
        }
    }
    __syncthreads();   // done reading sw2/a1s -> reuse S as C

    int* Cs = (int*)S;  // [128 pix][68] int
    #pragma unroll
    for (int h = 0; h < 2; h++) {
        int row = h * 64 + wm * 16 + (lane >> 2);
        #pragma unroll
        for (int nt = 0; nt < 4; nt++) {
            int col = wn * 32 + nt * 8 + ((lane & 3) << 1);
            int2 v0 = make_int2(c[h][nt][0], c[h][nt][1]);
            int2 v1 = make_int2(c[h][nt][2], c[h][nt][3]);
            *(int2*)(Cs + row * 68 + col) = v0;
            *(int2*)(Cs + (row + 8) * 68 + col) = v1;
        }
    }
    __syncthreads();

    float mul2 = s_in * (g_maxabs[1] / 7.0f);
    for (int o = tid; o < 800; o += 256) {      // one output byte = two s4 outputs
        int nib[2];
        #pragma unroll
        for (int h2 = 0; h2 < 2; h2++) {
            int e = 2 * o + h2;
            int oc = e / 25, p = e - oc * 25;
            int py = p / 5, px = p - py * 5;
            int cp0 = (2 * py) * 11 + 2 * px;
            int m = Cs[cp0 * 68 + oc];
            m = max(m, Cs[(cp0 + 1) * 68 + oc]);
            m = max(m, Cs[(cp0 + 11) * 68 + oc]);
            m = max(m, Cs[(cp0 + 12) * 68 + oc]);
            float v = (float)m * mul2;
            int q = clampi((int)rintf(v * inv_a2), 0, 15);
            float v2 = (float)q * s_a2;
            nib[h2] = clampi((int)rintf(v2 * inv_in), -8, 7);
        }
        g_act2[b * 832 + o] = (int8_t)pack2n(nib[0], nib[1]);
    }
}

// ---------------- fc1: s4 IMMA GEMM [1024,1600] x [4096,1600]^T ----------------
// Rows s4-packed (832B, zero-padded). Grid (64,16) = 1024 CTAs, 128 threads
// (4 warps 2x2), warp tile 32x32, BK=64 bytes = K=128 s4. 13 K-tiles.
__global__ __launch_bounds__(128) void fc1_imma_k(const float* __restrict__ s_in_p,
                                                  const float* __restrict__ s_a3_p) {
    __shared__ __align__(16) int8_t sA[2][64 * 80];
    __shared__ __align__(16) int8_t sB[2][64 * 80];
    const int BUFB = 64 * 80;

    int tid = threadIdx.x, lane = tid & 31, wid = tid >> 5;
    int wm = wid >> 1, wn = wid & 1;
    int bm = blockIdx.y, bn = blockIdx.x;

    int lrow = tid >> 1, lseg2 = (tid & 1) << 1;
    const char* gA0 = (const char*)g_act2 + (size_t)(bm * 64 + lrow) * 832 + lseg2 * 16;
    const char* gB0 = (const char*)g_qwl1 + (size_t)(bn * 64 + lrow) * 832 + lseg2 * 16;
    uint32_t smA0 = smem_u32(&sA[0][0]) + lrow * 80 + lseg2 * 16;
    uint32_t smB0 = smem_u32(&sB[0][0]) + lrow * 80 + lseg2 * 16;

    int c[2][4][4];
    #pragma unroll
    for (int i = 0; i < 2; i++)
        #pragma unroll
        for (int j = 0; j < 4; j++)
            #pragma unroll
            for (int e = 0; e < 4; e++) c[i][j][e] = 0;

    CPA16(smA0, gA0);
    CPA16(smA0 + 16, gA0 + 16);
    CPA16(smB0, gB0);
    CPA16(smB0 + 16, gB0 + 16);
    CPC(); CPW0();
    __syncthreads();

    uint32_t saL = smem_u32(&sA[0][0]) + (wm * 32 + (lane & 15)) * 80 + ((lane >> 4) << 4);
    uint32_t sbL = smem_u32(&sB[0][0])
                 + (wn * 32 + (lane & 7) + ((lane >> 4) << 3)) * 80
                 + (((lane >> 3) & 1) << 4);

    int buf = 0;
    for (int kt = 0; kt < 13; kt++) {
        if (kt < 12) {
            int nb = buf ^ 1;
            const char* ga = gA0 + (kt + 1) * 64;
            const char* gb = gB0 + (kt + 1) * 64;
            uint32_t da = smA0 + nb * BUFB, db = smB0 + nb * BUFB;
            CPA16(da, ga);
            CPA16(da + 16, ga + 16);
            CPA16(db, gb);
            CPA16(db + 16, gb + 16);
            CPC();
        }
        uint32_t sa = saL + buf * BUFB;
        uint32_t sb = sbL + buf * BUFB;
        #pragma unroll
        for (int ks = 0; ks < 2; ks++) {
            uint32_t a[2][4], bb[4][2];
            #pragma unroll
            for (int mt = 0; mt < 2; mt++)
                ldsm4(a[mt][0], a[mt][1], a[mt][2], a[mt][3],
                      sa + mt * 16 * 80 + ks * 32);
            #pragma unroll
            for (int j = 0; j < 2; j++) {
                uint32_t r0, r1, r2, r3;
                ldsm4(r0, r1, r2, r3, sb + j * 16 * 80 + ks * 32);
                bb[2 * j][0] = r0;     bb[2 * j][1] = r1;
                bb[2 * j + 1][0] = r2; bb[2 * j + 1][1] = r3;
            }
            #pragma unroll
            for (int mt = 0; mt < 2; mt++)
                #pragma unroll
                for (int nt = 0; nt < 4; nt++)
                    imma16864s4(c[mt][nt], a[mt], bb[nt]);
        }
        if (kt < 12) {
            CPW0();
            __syncthreads();
            buf ^= 1;
        }
    }

    float s_in = *s_in_p, s_a3 = *s_a3_p;
    float mul = s_in * (g_maxabs[2] / 7.0f);
    float isa3 = 1.0f / s_a3;  // power of two -> exact
    int r0 = bm * 64 + wm * 32 + (lane >> 2);
    int c0 = bn * 64 + wn * 32 + ((lane & 3) << 1);
    #pragma unroll
    for (int mt = 0; mt < 2; mt++) {
        #pragma unroll
        for (int nt = 0; nt < 4; nt++) {
            int rr = r0 + mt * 16, cc = c0 + nt * 8;
            int* cf = c[mt][nt];
            uchar2 lo, hi;
            lo.x = (uint8_t)clampi((int)rintf((float)cf[0] * mul * isa3), 0, 15);
            lo.y = (uint8_t)clampi((int)rintf((float)cf[1] * mul * isa3), 0, 15);
            hi.x = (uint8_t)clampi((int)rintf((float)cf[2] * mul * isa3), 0, 15);
            hi.y = (uint8_t)clampi((int)rintf((float)cf[3] * mul * isa3), 0, 15);
            *(uchar2*)(g_act3 + rr * 4096 + cc) = lo;
            *(uchar2*)(g_act3 + (rr + 8) * 4096 + cc) = hi;
        }
    }
}

// ---------------- fc2: [1024,4096] x [10,4096]^T -> out (+ scale reset tail) ----
__global__ void fc2_k(const float* __restrict__ s_a3_p, float* __restrict__ out) {
    int b = blockIdx.x;
    int wj = threadIdx.x >> 5, lane = threadIdx.x & 31;
    const int* ar = (const int*)(g_act3 + b * 4096);
    const int* wr = (const int*)(g_qwl2 + wj * 4096);
    int acc = 0;
    for (int t = lane; t < 1024; t += 32)
        acc = __dp4a(ar[t], wr[t], acc);
    #pragma unroll
    for (int o = 16; o; o >>= 1) acc += __shfl_xor_sync(0xffffffffu, acc, o);
    if (lane == 0)
        out[b * 10 + wj] = (float)acc * (*s_a3_p) * (g_maxabs[3] / 7.0f);

    // last-finishing block resets scales for the next replay (deterministic)
    __syncthreads();
    if (threadIdx.x == 0) {
        __threadfence();
        if (atomicAdd(&g_cnt2, 1) == (int)gridDim.x - 1) {
            g_maxabs[0] = 0.0f; g_maxabs[1] = 0.0f;
            g_maxabs[2] = 0.0f; g_maxabs[3] = 0.0f;
            g_cnt2 = 0;
            __threadfence();
        }
    }
}

// ---------------- launcher ----------------
extern "C" void kernel_launch(void* const* d_in, const int* in_sizes, int n_in,
                              void* d_out, int out_size) {
    const float* x    = (const float*)d_in[0];
    const float* w1   = (const float*)d_in[1];
    const float* w2   = (const float*)d_in[2];
    const float* wl1  = (const float*)d_in[3];
    const float* wl2  = (const float*)d_in[4];
    const float* s_in = (const float*)d_in[5];
    const float* s_a1 = (const float*)d_in[6];
    const float* s_a2 = (const float*)d_in[7];
    const float* s_a3 = (const float*)d_in[8];
    float* out = (float*)d_out;

    prep1_k<<<1475, 256>>>(w1, w2, wl1, wl2, x, s_in);   // maxabs + quant_x
    quant_w_k<<<2282, 256>>>(w1, w2, wl1, wl2);
    conv12_k<<<1024, 256>>>(s_in, s_a1, s_a2);
    fc1_imma_k<<<dim3(64, 16), 128>>>(s_in, s_a3);       // 4th launch -> ncu capture
    fc2_k<<<1024, 320>>>(s_a3, out);
}

// round 14
// speedup vs baseline: 1.9000x; 1.9000x over previous
#include <cuda_runtime.h>
#include <cuda_bf16.h>
#include <stdint.h>

#define NB 1024

// ---------------- scratch (no allocations allowed) ----------------
__device__ float g_maxabs[4];                           // zero-init; reset by fc2 tail
__device__ int   g_cnt2;                                // fc2 completion ticket
__device__ __align__(16) int8_t g_qx  [NB * 784];       // quantized input q
__device__ __align__(16) int8_t g_qw1 [32 * 9];         // [oc][kpos]
__device__ __align__(16) int8_t g_qw2 [64 * 9 * 32];    // [oc][kpos 9][ic 32] rows of 288
__device__ __align__(16) int8_t g_act2[NB * 1600];      // fc1 A (s8 q) [b][oc*25+p]
__device__ __align__(16) int8_t g_qwl1[4096 * 1600];    // fc1 B (s8 q) [n][k]
__device__ __align__(16) int8_t g_act3[NB * 4096];      // fc1 output q (0..15)
__device__ __align__(16) int8_t g_qwl2[10 * 4096];      // [n][k]

__device__ __forceinline__ int clampi(int v, int lo, int hi) {
    return max(lo, min(hi, v));
}
__device__ __forceinline__ int dp4(uint32_t a, uint32_t b, int c) {
    return __dp4a((int)a, (int)b, c);   // signed byte dot-product
}
__device__ __forceinline__ uint32_t smem_u32(const void* p) {
    return (uint32_t)__cvta_generic_to_shared(p);
}
__device__ __forceinline__ void ldsm4(uint32_t& r0, uint32_t& r1, uint32_t& r2,
                                      uint32_t& r3, uint32_t a) {
    asm volatile("ldmatrix.sync.aligned.m8n8.x4.shared.b16 {%0,%1,%2,%3}, [%4];\n"
                 : "=r"(r0), "=r"(r1), "=r"(r2), "=r"(r3) : "r"(a));
}
__device__ __forceinline__ void imma16832(int* c, const uint32_t* a, const uint32_t* b) {
    asm volatile(
        "mma.sync.aligned.m16n8k32.row.col.s32.s8.s8.s32 "
        "{%0,%1,%2,%3},{%4,%5,%6,%7},{%8,%9},{%0,%1,%2,%3};\n"
        : "+r"(c[0]), "+r"(c[1]), "+r"(c[2]), "+r"(c[3])
        : "r"(a[0]), "r"(a[1]), "r"(a[2]), "r"(a[3]), "r"(b[0]), "r"(b[1]));
}
#define CPA16(dst, src) \
    asm volatile("cp.async.cg.shared.global [%0], [%1], 16;\n" ::"r"(dst), "l"(src))
#define CPC()  asm volatile("cp.async.commit_group;\n")
#define CPW0() asm volatile("cp.async.wait_group 0;\n")

// ---------------- maxabs (+ fused quant_x) ----------------
__device__ void maxabs_dev(const float* __restrict__ w, int n4, int idx,
                           int bid, int nblocks) {
    const float4* w4 = (const float4*)w;
    int G = nblocks * 256;
    int i0 = bid * 256 + threadIdx.x;
    float m0 = 0.f, m1 = 0.f, m2 = 0.f, m3 = 0.f;
    for (int i = i0; i < n4; i += 4 * G) {
        float4 v = w4[i];
        m0 = fmaxf(m0, fmaxf(fmaxf(fabsf(v.x), fabsf(v.y)),
                             fmaxf(fabsf(v.z), fabsf(v.w))));
        int i1 = i + G;
        if (i1 < n4) {
            float4 u = w4[i1];
            m1 = fmaxf(m1, fmaxf(fmaxf(fabsf(u.x), fabsf(u.y)),
                                 fmaxf(fabsf(u.z), fabsf(u.w))));
        }
        int i2 = i + 2 * G;
        if (i2 < n4) {
            float4 u = w4[i2];
            m2 = fmaxf(m2, fmaxf(fmaxf(fabsf(u.x), fabsf(u.y)),
                                 fmaxf(fabsf(u.z), fabsf(u.w))));
        }
        int i3 = i + 3 * G;
        if (i3 < n4) {
            float4 u = w4[i3];
            m3 = fmaxf(m3, fmaxf(fmaxf(fabsf(u.x), fabsf(u.y)),
                                 fmaxf(fabsf(u.z), fabsf(u.w))));
        }
    }
    float m = fmaxf(fmaxf(m0, m1), fmaxf(m2, m3));
    #pragma unroll
    for (int o = 16; o; o >>= 1) m = fmaxf(m, __shfl_xor_sync(0xffffffffu, m, o));
    __shared__ float sm[8];
    int lane = threadIdx.x & 31, wid = threadIdx.x >> 5;
    if (lane == 0) sm[wid] = m;
    __syncthreads();
    if (wid == 0) {
        m = (lane < 8) ? sm[lane] : 0.0f;
        #pragma unroll
        for (int o = 4; o; o >>= 1) m = fmaxf(m, __shfl_xor_sync(0xffffffffu, m, o));
        if (lane == 0) atomicMax((int*)&g_maxabs[idx], __float_as_int(m));
    }
}

// blocks: [0,1024) wl1 max, [1024,1042) w2, [1042,1082) wl2, [1082] w1,
//         [1083, 1475) quant_x (each thread covers 2 elements: i, i+100352)
__global__ void prep1_k(const float* __restrict__ w1,
                        const float* __restrict__ w2,
                        const float* __restrict__ wl1,
                        const float* __restrict__ wl2,
                        const float* __restrict__ x,
                        const float* __restrict__ s_in_p) {
    int bx = blockIdx.x;
    if (bx < 1024)        maxabs_dev(wl1, (4096 * 1600) >> 2, 2, bx, 1024);
    else if (bx < 1042)   maxabs_dev(w2, (64 * 32 * 9) >> 2, 1, bx - 1024, 18);
    else if (bx < 1082)   maxabs_dev(wl2, (10 * 4096) >> 2, 3, bx - 1042, 40);
    else if (bx == 1082)  maxabs_dev(w1, (32 * 9) >> 2, 0, 0, 1);
    else {
        float inv = 1.0f / *s_in_p;  // s_in power of two -> exact
        const int n4 = (NB * 784) >> 2;  // 200704
        const int half = 392 * 256;      // 100352
        const float4* x4 = (const float4*)x;
        char4* q4 = (char4*)g_qx;
        int i = (bx - 1083) * 256 + (int)threadIdx.x;
        #pragma unroll
        for (int rep = 0; rep < 2; rep++) {
            int ii = i + rep * half;
            if (ii < n4) {
                float4 v = x4[ii];
                char4 q;
                q.x = (char)clampi((int)rintf(v.x * inv), -8, 7);
                q.y = (char)clampi((int)rintf(v.y * inv), -8, 7);
                q.z = (char)clampi((int)rintf(v.z * inv), -8, 7);
                q.w = (char)clampi((int)rintf(v.w * inv), -8, 7);
                q4[ii] = q;
            }
        }
    }
}

// small weights only: blocks [0,160) wl2, [160,232) w2, [232,234) w1
__global__ void quant_small_k(const float* __restrict__ w1,
                              const float* __restrict__ w2,
                              const float* __restrict__ wl2) {
    int bx = blockIdx.x, tid = threadIdx.x;
    if (bx < 160) {
        float s = g_maxabs[3] / 7.0f;
        int i = bx * 256 + tid;
        if (i < 10 * 4096)
            g_qwl2[i] = (int8_t)clampi((int)rintf(wl2[i] / s), -7, 7);
    } else if (bx < 232) {
        float s = g_maxabs[1] / 7.0f;
        int i = (bx - 160) * 256 + tid;
        if (i < 64 * 9 * 32) {
            int oc = i / 288, r = i % 288;
            int pos = r >> 5, ic = r & 31;
            float v = w2[(oc * 32 + ic) * 9 + pos];
            g_qw2[i] = (int8_t)clampi((int)rintf(v / s), -7, 7);
        }
    } else {
        float s = g_maxabs[0] / 7.0f;
        int i = (bx - 232) * 256 + tid;
        if (i < 32 * 9)
            g_qw1[i] = (int8_t)clampi((int)rintf(w1[i] / s), -7, 7);
    }
}

// ---------------- fused conv1+pool+fq -> conv2(IMMA)+pool+fq  [+ wl1 quant] ----
// blocks [0,1024): conv path per image. blocks [1024,3072): wl1 s8 quantization
// (independent work overlapped with the convs).
#define A1S 48
#define WS2 304
__global__ __launch_bounds__(256) void conv12_k(const float* __restrict__ s_in_p,
                                                const float* __restrict__ s_a1_p,
                                                const float* __restrict__ s_a2_p,
                                                const float* __restrict__ wl1) {
    __shared__ __align__(16) int8_t S[35072];
    int b = blockIdx.x, tid = threadIdx.x;

    if (b >= 1024) {   // ---- wl1 quantization, overlapped ----
        float rinv = 1.0f / (g_maxabs[2] / 7.0f);
        const int n4 = (4096 * 1600) >> 2;
        const float4* w4 = (const float4*)wl1;
        char4* o4 = (char4*)g_qwl1;
        for (int i = (b - 1024) * 256 + tid; i < n4; i += 2048 * 256) {
            float4 v = w4[i];
            char4 q;
            q.x = (char)clampi((int)rintf(v.x * rinv), -7, 7);
            q.y = (char)clampi((int)rintf(v.y * rinv), -7, 7);
            q.z = (char)clampi((int)rintf(v.z * rinv), -7, 7);
            q.w = (char)clampi((int)rintf(v.w * rinv), -7, 7);
            o4[i] = q;
        }
        return;
    }

    int8_t* sw2 = S;                             // 64*304 = 19456
    int8_t* a1s = S + 19456;                     // act1 tile (stride 48), 8576
    int8_t* sx  = S + 28032;                     // 784
    uint32_t* swp = (uint32_t*)(S + 28832);      // packed conv1 weights, 96 u32
    int lane = tid & 31, wid = tid >> 5;

    for (int idx = tid; idx < 1152; idx += 256) {
        int row = idx / 18, seg = idx % 18;
        CPA16(smem_u32(sw2 + row * WS2 + seg * 16),
              (const char*)g_qw2 + row * 288 + seg * 16);
    }
    CPC();
    {
        const int* gx = (const int*)(g_qx + b * 784);
        int* sxi = (int*)sx;
        for (int i = tid; i < 196; i += 256) sxi[i] = gx[i];
        if (tid < 96) {  // pack w1[oc][ky][0..2] -> u32 with zero 4th byte
            int oc = tid / 3, ky = tid - oc * 3;
            const uint8_t* wp = (const uint8_t*)g_qw1 + oc * 9 + ky * 3;
            swp[tid] = (uint32_t)wp[0] | ((uint32_t)wp[1] << 8)
                     | ((uint32_t)wp[2] << 16);
        }
    }
    __syncthreads();

    float s_in = *s_in_p, s_a1 = *s_a1_p, s_a2 = *s_a2_p;
    float inv_in = 1.0f / s_in, inv_a1 = 1.0f / s_a1, inv_a2 = 1.0f / s_a2;
    float mul1 = s_in * (g_maxabs[0] / 7.0f);

    if (tid < 169) {
        int py = tid / 13, px = tid - py * 13;
        int c0 = 2 * px;
        uint32_t V[4];
        #pragma unroll
        for (int r = 0; r < 4; r++) {
            int boff = (2 * py + r) * 28 + c0;
            int b4 = boff & ~3;
            uint32_t lo = *(const uint32_t*)(sx + b4);
            if (boff & 2) {
                uint32_t hi = *(const uint32_t*)(sx + b4 + 4);
                V[r] = __funnelshift_r(lo, hi, 16);
            } else {
                V[r] = lo;
            }
        }
        uint32_t Q[4][2];
        #pragma unroll
        for (int r = 0; r < 4; r++) {
            Q[r][0] = V[r] & 0x00FFFFFFu;
            Q[r][1] = (V[r] >> 8) & 0x00FFFFFFu;
        }
        int8_t* arow = a1s + tid * A1S;
        #pragma unroll
        for (int g = 0; g < 8; g++) {
            uint32_t pk = 0;
            #pragma unroll
            for (int j = 0; j < 4; j++) {
                int oc = g * 4 + j;
                uint32_t w0 = swp[oc * 3 + 0], w1 = swp[oc * 3 + 1],
                         w2 = swp[oc * 3 + 2];
                int a00 = dp4(Q[0][0], w0, dp4(Q[1][0], w1, dp4(Q[2][0], w2, 0)));
                int a01 = dp4(Q[0][1], w0, dp4(Q[1][1], w1, dp4(Q[2][1], w2, 0)));
                int a10 = dp4(Q[1][0], w0, dp4(Q[2][0], w1, dp4(Q[3][0], w2, 0)));
                int a11 = dp4(Q[1][1], w0, dp4(Q[2][1], w1, dp4(Q[3][1], w2, 0)));
                int m = max(max(a00, a01), max(a10, a11));
                float v = (float)m * mul1;
                int q = clampi((int)rintf(v * inv_a1), 0, 15);
                float v2 = (float)q * s_a1;
                int q2 = clampi((int)rintf(v2 * inv_in), -8, 7);
                pk |= ((uint32_t)q2 & 0xFFu) << (j * 8);
            }
            *(uint32_t*)(arow + g * 4) = pk;
        }
    }
    CPW0();
    __syncthreads();

    // conv2 IMMA: A[128 conv-pix][288] gathered from a1s, B = sw2 [64 oc][288]
    int wm = wid >> 1, wn = wid & 1;
    int c[2][4][4];
    #pragma unroll
    for (int h = 0; h < 2; h++)
        #pragma unroll
        for (int nt = 0; nt < 4; nt++)
            #pragma unroll
            for (int e = 0; e < 4; e++) c[h][nt][e] = 0;

    uint32_t bbase = smem_u32(sw2)
                   + (wn * 32 + (lane & 7) + ((lane >> 4) << 3)) * WS2
                   + (((lane >> 3) & 1) << 4);
    uint32_t abase_h[2];
    {
        int khalf = lane >> 4;
        #pragma unroll
        for (int h = 0; h < 2; h++) {
            int p = h * 64 + wm * 16 + (lane & 15);
            int cy = p / 11, cx = p % 11;
            abase_h[h] = smem_u32(a1s) + (cy * 13 + cx) * A1S + khalf * 16;
        }
    }

    #pragma unroll
    for (int h = 0; h < 2; h++) {
        #pragma unroll
        for (int ks = 0; ks < 9; ks++) {
            int ky = ks / 3, kx = ks % 3;
            uint32_t a[4];
            ldsm4(a[0], a[1], a[2], a[3], abase_h[h] + (ky * 13 + kx) * A1S);
            uint32_t bb[4][2];
            #pragma unroll
            for (int j = 0; j < 2; j++) {
                uint32_t r0, r1, r2, r3;
                ldsm4(r0, r1, r2, r3, bbase + j * 16 * WS2 + ks * 32);
                bb[2 * j][0] = r0;     bb[2 * j][1] = r1;
                bb[2 * j + 1][0] = r2; bb[2 * j + 1][1] = r3;
            }
            #pragma unroll
            for (int nt = 0; nt < 4; nt++)
                imma16832(c[h][nt], a, bb[nt]);
        }
    }
    __syncthreads();   // done reading sw2/a1s -> reuse S as C

    int* Cs = (int*)S;  // [128 pix][68] int
    #pragma unroll
    for (int h = 0; h < 2; h++) {
        int row = h * 64 + wm * 16 + (lane >> 2);
        #pragma unroll
        for (int nt = 0; nt < 4; nt++) {
            int col = wn * 32 + nt * 8 + ((lane & 3) << 1);
            int2 v0 = make_int2(c[h][nt][0], c[h][nt][1]);
            int2 v1 = make_int2(c[h][nt][2], c[h][nt][3]);
            *(int2*)(Cs + row * 68 + col) = v0;
            *(int2*)(Cs + (row + 8) * 68 + col) = v1;
        }
    }
    __syncthreads();

    float mul2 = s_in * (g_maxabs[1] / 7.0f);
    for (int o = tid; o < 1600; o += 256) {
        int oc = o / 25, p = o - oc * 25;
        int py = p / 5, px = p - py * 5;
        int cp0 = (2 * py) * 11 + 2 * px;
        int m = Cs[cp0 * 68 + oc];
        m = max(m, Cs[(cp0 + 1) * 68 + oc]);
        m = max(m, Cs[(cp0 + 11) * 68 + oc]);
        m = max(m, Cs[(cp0 + 12) * 68 + oc]);
        float v = (float)m * mul2;
        int q = clampi((int)rintf(v * inv_a2), 0, 15);
        float v2 = (float)q * s_a2;
        int q2 = clampi((int)rintf(v2 * inv_in), -8, 7);
        g_act2[b * 1600 + o] = (int8_t)q2;
    }
}

// ---------------- fc1: s8 IMMA GEMM, 64x64 tiles, BK=160 (1600 = 10x160) -------
// Grid (64, 16) = 1024 CTAs, 128 threads (4 warps 2x2), warp tile 32x32.
// Row stride 176B (11x16; 11r mod 8 cycles all residues -> ldmatrix conflict-free).
#define FRS 176
__global__ __launch_bounds__(128) void fc1_imma_k(const float* __restrict__ s_in_p,
                                                  const float* __restrict__ s_a3_p) {
    __shared__ __align__(16) int8_t sA[2][64 * FRS];
    __shared__ __align__(16) int8_t sB[2][64 * FRS];
    const int BUFB = 64 * FRS;

    int tid = threadIdx.x, lane = tid & 31, wid = tid >> 5;
    int wm = wid >> 1, wn = wid & 1;
    int bm = blockIdx.y, bn = blockIdx.x;

    int lrow = tid >> 1, lhalf = tid & 1;   // 64 rows x 2 halves of 80B
    const char* gA0 = (const char*)g_act2 + (size_t)(bm * 64 + lrow) * 1600 + lhalf * 80;
    const char* gB0 = (const char*)g_qwl1 + (size_t)(bn * 64 + lrow) * 1600 + lhalf * 80;
    uint32_t smA0 = smem_u32(&sA[0][0]) + lrow * FRS + lhalf * 80;
    uint32_t smB0 = smem_u32(&sB[0][0]) + lrow * FRS + lhalf * 80;

    int c[2][4][4];
    #pragma unroll
    for (int i = 0; i < 2; i++)
        #pragma unroll
        for (int j = 0; j < 4; j++)
            #pragma unroll
            for (int e = 0; e < 4; e++) c[i][j][e] = 0;

    #pragma unroll
    for (int j = 0; j < 5; j++) {
        CPA16(smA0 + j * 16, gA0 + j * 16);
        CPA16(smB0 + j * 16, gB0 + j * 16);
    }
    CPC(); CPW0();
    __syncthreads();

    uint32_t saL = smem_u32(&sA[0][0]) + (wm * 32 + (lane & 15)) * FRS + ((lane >> 4) << 4);
    uint32_t sbL = smem_u32(&sB[0][0])
                 + (wn * 32 + (lane & 7) + ((lane >> 4) << 3)) * FRS
                 + (((lane >> 3) & 1) << 4);

    int buf = 0;
    for (int kt = 0; kt < 10; kt++) {
        if (kt < 9) {
            int nb = buf ^ 1;
            const char* ga = gA0 + (kt + 1) * 160;
            const char* gb = gB0 + (kt + 1) * 160;
            uint32_t da = smA0 + nb * BUFB, db = smB0 + nb * BUFB;
            #pragma unroll
            for (int j = 0; j < 5; j++) {
                CPA16(da + j * 16, ga + j * 16);
                CPA16(db + j * 16, gb + j * 16);
            }
            CPC();
        }
        uint32_t sa = saL + buf * BUFB;
        uint32_t sb = sbL + buf * BUFB;
        #pragma unroll
        for (int ks = 0; ks < 5; ks++) {
            uint32_t a[2][4], bb[4][2];
            #pragma unroll
            for (int mt = 0; mt < 2; mt++)
                ldsm4(a[mt][0], a[mt][1], a[mt][2], a[mt][3],
                      sa + mt * 16 * FRS + ks * 32);
            #pragma unroll
            for (int j = 0; j < 2; j++) {
                uint32_t r0, r1, r2, r3;
                ldsm4(r0, r1, r2, r3, sb + j * 16 * FRS + ks * 32);
                bb[2 * j][0] = r0;     bb[2 * j][1] = r1;
                bb[2 * j + 1][0] = r2; bb[2 * j + 1][1] = r3;
            }
            #pragma unroll
            for (int mt = 0; mt < 2; mt++)
                #pragma unroll
                for (int nt = 0; nt < 4; nt++)
                    imma16832(c[mt][nt], a[mt], bb[nt]);
        }
        if (kt < 9) {
            CPW0();
            __syncthreads();
            buf ^= 1;
        }
    }

    float s_in = *s_in_p, s_a3 = *s_a3_p;
    float mul = s_in * (g_maxabs[2] / 7.0f);
    float isa3 = 1.0f / s_a3;  // power of two -> exact
    int r0 = bm * 64 + wm * 32 + (lane >> 2);
    int c0 = bn * 64 + wn * 32 + ((lane & 3) << 1);
    #pragma unroll
    for (int mt = 0; mt < 2; mt++) {
        #pragma unroll
        for (int nt = 0; nt < 4; nt++) {
            int rr = r0 + mt * 16, cc = c0 + nt * 8;
            int* cf = c[mt][nt];
            uchar2 lo, hi;
            lo.x = (uint8_t)clampi((int)rintf((float)cf[0] * mul * isa3), 0, 15);
            lo.y = (uint8_t)clampi((int)rintf((float)cf[1] * mul * isa3), 0, 15);
            hi.x = (uint8_t)clampi((int)rintf((float)cf[2] * mul * isa3), 0, 15);
            hi.y = (uint8_t)clampi((int)rintf((float)cf[3] * mul * isa3), 0, 15);
            *(uchar2*)(g_act3 + rr * 4096 + cc) = lo;
            *(uchar2*)(g_act3 + (rr + 8) * 4096 + cc) = hi;
        }
    }
}

// ---------------- fc2: [1024,4096] x [10,4096]^T -> out (+ scale reset tail) ----
__global__ void fc2_k(const float* __restrict__ s_a3_p, float* __restrict__ out) {
    int b = blockIdx.x;
    int wj = threadIdx.x >> 5, lane = threadIdx.x & 31;
    const int* ar = (const int*)(g_act3 + b * 4096);
    const int* wr = (const int*)(g_qwl2 + wj * 4096);
    int acc = 0;
    for (int t = lane; t < 1024; t += 32)
        acc = __dp4a(ar[t], wr[t], acc);
    #pragma unroll
    for (int o = 16; o; o >>= 1) acc += __shfl_xor_sync(0xffffffffu, acc, o);
    if (lane == 0)
        out[b * 10 + wj] = (float)acc * (*s_a3_p) * (g_maxabs[3] / 7.0f);

    // last-finishing block resets scales for the next replay (deterministic)
    __syncthreads();
    if (threadIdx.x == 0) {
        __threadfence();
        if (atomicAdd(&g_cnt2, 1) == (int)gridDim.x - 1) {
            g_maxabs[0] = 0.0f; g_maxabs[1] = 0.0f;
            g_maxabs[2] = 0.0f; g_maxabs[3] = 0.0f;
            g_cnt2 = 0;
            __threadfence();
        }
    }
}

// ---------------- launcher ----------------
extern "C" void kernel_launch(void* const* d_in, const int* in_sizes, int n_in,
                              void* d_out, int out_size) {
    const float* x    = (const float*)d_in[0];
    const float* w1   = (const float*)d_in[1];
    const float* w2   = (const float*)d_in[2];
    const float* wl1  = (const float*)d_in[3];
    const float* wl2  = (const float*)d_in[4];
    const float* s_in = (const float*)d_in[5];
    const float* s_a1 = (const float*)d_in[6];
    const float* s_a2 = (const float*)d_in[7];
    const float* s_a3 = (const float*)d_in[8];
    float* out = (float*)d_out;

    prep1_k<<<1475, 256>>>(w1, w2, wl1, wl2, x, s_in);     // maxabs + quant_x
    quant_small_k<<<234, 256>>>(w1, w2, wl2);              // w1/w2/wl2 quant
    conv12_k<<<3072, 256>>>(s_in, s_a1, s_a2, wl1);        // conv + wl1 quant overlap
    fc1_imma_k<<<dim3(64, 16), 128>>>(s_in, s_a3);         // 4th launch -> ncu capture
    fc2_k<<<1024, 320>>>(s_a3, out);
}

// round 15
// speedup vs baseline: 2.0642x; 1.0864x over previous
#include <cuda_runtime.h>
#include <cuda_bf16.h>
#include <stdint.h>

#define NB 1024

// ---------------- scratch (no allocations allowed) ----------------
__device__ float g_maxabs[4];                           // zero-init; reset by fc2 tail
__device__ int   g_cnt2;                                // fc2 completion ticket
__device__ __align__(16) int8_t g_qx  [NB * 784];       // quantized input q
__device__ __align__(16) int8_t g_qw1 [32 * 9];         // [oc][kpos]
__device__ __align__(16) int8_t g_qw2 [64 * 9 * 32];    // [oc][kpos 9][ic 32] rows of 288
__device__ __align__(16) int8_t g_act2[NB * 1600];      // fc1 A (s8 q) [b][oc*25+p]
__device__ __align__(16) int8_t g_qwl1[4096 * 1600];    // fc1 B (s8 q) [n][k]
__device__ __align__(16) int8_t g_act3[NB * 4096];      // fc1 output q (0..15)
__device__ __align__(16) int8_t g_qwl2[10 * 4096];      // [n][k]

__device__ __forceinline__ int clampi(int v, int lo, int hi) {
    return max(lo, min(hi, v));
}
__device__ __forceinline__ int dp4(uint32_t a, uint32_t b, int c) {
    return __dp4a((int)a, (int)b, c);   // signed byte dot-product
}
__device__ __forceinline__ uint32_t smem_u32(const void* p) {
    return (uint32_t)__cvta_generic_to_shared(p);
}
__device__ __forceinline__ void ldsm4(uint32_t& r0, uint32_t& r1, uint32_t& r2,
                                      uint32_t& r3, uint32_t a) {
    asm volatile("ldmatrix.sync.aligned.m8n8.x4.shared.b16 {%0,%1,%2,%3}, [%4];\n"
                 : "=r"(r0), "=r"(r1), "=r"(r2), "=r"(r3) : "r"(a));
}
__device__ __forceinline__ void imma16832(int* c, const uint32_t* a, const uint32_t* b) {
    asm volatile(
        "mma.sync.aligned.m16n8k32.row.col.s32.s8.s8.s32 "
        "{%0,%1,%2,%3},{%4,%5,%6,%7},{%8,%9},{%0,%1,%2,%3};\n"
        : "+r"(c[0]), "+r"(c[1]), "+r"(c[2]), "+r"(c[3])
        : "r"(a[0]), "r"(a[1]), "r"(a[2]), "r"(a[3]), "r"(b[0]), "r"(b[1]));
}
#define CPA16(dst, src) \
    asm volatile("cp.async.cg.shared.global [%0], [%1], 16;\n" ::"r"(dst), "l"(src))
#define CPC()  asm volatile("cp.async.commit_group;\n")
#define CPW0() asm volatile("cp.async.wait_group 0;\n")
#define CPW1() asm volatile("cp.async.wait_group 1;\n")

// ---------------- maxabs (+ fused quant_x) ----------------
__device__ void maxabs_dev(const float* __restrict__ w, int n4, int idx,
                           int bid, int nblocks) {
    const float4* w4 = (const float4*)w;
    int G = nblocks * 256;
    int i0 = bid * 256 + threadIdx.x;
    float m0 = 0.f, m1 = 0.f, m2 = 0.f, m3 = 0.f;
    for (int i = i0; i < n4; i += 4 * G) {
        float4 v = w4[i];
        m0 = fmaxf(m0, fmaxf(fmaxf(fabsf(v.x), fabsf(v.y)),
                             fmaxf(fabsf(v.z), fabsf(v.w))));
        int i1 = i + G;
        if (i1 < n4) {
            float4 u = w4[i1];
            m1 = fmaxf(m1, fmaxf(fmaxf(fabsf(u.x), fabsf(u.y)),
                                 fmaxf(fabsf(u.z), fabsf(u.w))));
        }
        int i2 = i + 2 * G;
        if (i2 < n4) {
            float4 u = w4[i2];
            m2 = fmaxf(m2, fmaxf(fmaxf(fabsf(u.x), fabsf(u.y)),
                                 fmaxf(fabsf(u.z), fabsf(u.w))));
        }
        int i3 = i + 3 * G;
        if (i3 < n4) {
            float4 u = w4[i3];
            m3 = fmaxf(m3, fmaxf(fmaxf(fabsf(u.x), fabsf(u.y)),
                                 fmaxf(fabsf(u.z), fabsf(u.w))));
        }
    }
    float m = fmaxf(fmaxf(m0, m1), fmaxf(m2, m3));
    #pragma unroll
    for (int o = 16; o; o >>= 1) m = fmaxf(m, __shfl_xor_sync(0xffffffffu, m, o));
    __shared__ float sm[8];
    int lane = threadIdx.x & 31, wid = threadIdx.x >> 5;
    if (lane == 0) sm[wid] = m;
    __syncthreads();
    if (wid == 0) {
        m = (lane < 8) ? sm[lane] : 0.0f;
        #pragma unroll
        for (int o = 4; o; o >>= 1) m = fmaxf(m, __shfl_xor_sync(0xffffffffu, m, o));
        if (lane == 0) atomicMax((int*)&g_maxabs[idx], __float_as_int(m));
    }
}

// blocks: [0,1024) wl1 max, [1024,1042) w2, [1042,1082) wl2, [1082] w1,
//         [1083, 1475) quant_x (each thread covers 2 elements: i, i+100352)
__global__ void prep1_k(const float* __restrict__ w1,
                        const float* __restrict__ w2,
                        const float* __restrict__ wl1,
                        const float* __restrict__ wl2,
                        const float* __restrict__ x,
                        const float* __restrict__ s_in_p) {
    int bx = blockIdx.x;
    if (bx < 1024)        maxabs_dev(wl1, (4096 * 1600) >> 2, 2, bx, 1024);
    else if (bx < 1042)   maxabs_dev(w2, (64 * 32 * 9) >> 2, 1, bx - 1024, 18);
    else if (bx < 1082)   maxabs_dev(wl2, (10 * 4096) >> 2, 3, bx - 1042, 40);
    else if (bx == 1082)  maxabs_dev(w1, (32 * 9) >> 2, 0, 0, 1);
    else {
        float inv = 1.0f / *s_in_p;  // s_in power of two -> exact
        const int n4 = (NB * 784) >> 2;  // 200704
        const int half = 392 * 256;      // 100352
        const float4* x4 = (const float4*)x;
        char4* q4 = (char4*)g_qx;
        int i = (bx - 1083) * 256 + (int)threadIdx.x;
        #pragma unroll
        for (int rep = 0; rep < 2; rep++) {
            int ii = i + rep * half;
            if (ii < n4) {
                float4 v = x4[ii];
                char4 q;
                q.x = (char)clampi((int)rintf(v.x * inv), -8, 7);
                q.y = (char)clampi((int)rintf(v.y * inv), -8, 7);
                q.z = (char)clampi((int)rintf(v.z * inv), -8, 7);
                q.w = (char)clampi((int)rintf(v.w * inv), -8, 7);
                q4[ii] = q;
            }
        }
    }
}

// small weights only: blocks [0,160) wl2, [160,232) w2, [232,234) w1
__global__ void quant_small_k(const float* __restrict__ w1,
                              const float* __restrict__ w2,
                              const float* __restrict__ wl2) {
    int bx = blockIdx.x, tid = threadIdx.x;
    if (bx < 160) {
        float s = g_maxabs[3] / 7.0f;
        int i = bx * 256 + tid;
        if (i < 10 * 4096)
            g_qwl2[i] = (int8_t)clampi((int)rintf(wl2[i] / s), -7, 7);
    } else if (bx < 232) {
        float s = g_maxabs[1] / 7.0f;
        int i = (bx - 160) * 256 + tid;
        if (i < 64 * 9 * 32) {
            int oc = i / 288, r = i % 288;
            int pos = r >> 5, ic = r & 31;
            float v = w2[(oc * 32 + ic) * 9 + pos];
            g_qw2[i] = (int8_t)clampi((int)rintf(v / s), -7, 7);
        }
    } else {
        float s = g_maxabs[0] / 7.0f;
        int i = (bx - 232) * 256 + tid;
        if (i < 32 * 9)
            g_qw1[i] = (int8_t)clampi((int)rintf(w1[i] / s), -7, 7);
    }
}

// ---------------- fused conv1+pool+fq -> conv2(IMMA)+pool+fq  [+ wl1 quant] ----
// blocks [0,1024): conv path per image. blocks [1024,3072): wl1 s8 quantization.
#define A1S 48
#define WS2 304
__global__ __launch_bounds__(256) void conv12_k(const float* __restrict__ s_in_p,
                                                const float* __restrict__ s_a1_p,
                                                const float* __restrict__ s_a2_p,
                                                const float* __restrict__ wl1) {
    __shared__ __align__(16) int8_t S[35072];
    int b = blockIdx.x, tid = threadIdx.x;

    if (b >= 1024) {   // ---- wl1 quantization, overlapped ----
        float rinv = 1.0f / (g_maxabs[2] / 7.0f);
        const int n4 = (4096 * 1600) >> 2;
        const float4* w4 = (const float4*)wl1;
        char4* o4 = (char4*)g_qwl1;
        for (int i = (b - 1024) * 256 + tid; i < n4; i += 2048 * 256) {
            float4 v = w4[i];
            char4 q;
            q.x = (char)clampi((int)rintf(v.x * rinv), -7, 7);
            q.y = (char)clampi((int)rintf(v.y * rinv), -7, 7);
            q.z = (char)clampi((int)rintf(v.z * rinv), -7, 7);
            q.w = (char)clampi((int)rintf(v.w * rinv), -7, 7);
            o4[i] = q;
        }
        return;
    }

    int8_t* sw2 = S;                             // 64*304 = 19456
    int8_t* a1s = S + 19456;                     // act1 tile (stride 48), 8576
    int8_t* sx  = S + 28032;                     // 784
    uint32_t* swp = (uint32_t*)(S + 28832);      // packed conv1 weights, 96 u32
    int lane = tid & 31, wid = tid >> 5;

    for (int idx = tid; idx < 1152; idx += 256) {
        int row = idx / 18, seg = idx % 18;
        CPA16(smem_u32(sw2 + row * WS2 + seg * 16),
              (const char*)g_qw2 + row * 288 + seg * 16);
    }
    CPC();
    {
        const int* gx = (const int*)(g_qx + b * 784);
        int* sxi = (int*)sx;
        for (int i = tid; i < 196; i += 256) sxi[i] = gx[i];
        if (tid < 96) {  // pack w1[oc][ky][0..2] -> u32 with zero 4th byte
            int oc = tid / 3, ky = tid - oc * 3;
            const uint8_t* wp = (const uint8_t*)g_qw1 + oc * 9 + ky * 3;
            swp[tid] = (uint32_t)wp[0] | ((uint32_t)wp[1] << 8)
                     | ((uint32_t)wp[2] << 16);
        }
    }
    __syncthreads();

    float s_in = *s_in_p, s_a1 = *s_a1_p, s_a2 = *s_a2_p;
    float inv_in = 1.0f / s_in, inv_a1 = 1.0f / s_a1, inv_a2 = 1.0f / s_a2;
    float mul1 = s_in * (g_maxabs[0] / 7.0f);

    if (tid < 169) {
        int py = tid / 13, px = tid - py * 13;
        int c0 = 2 * px;
        uint32_t V[4];
        #pragma unroll
        for (int r = 0; r < 4; r++) {
            int boff = (2 * py + r) * 28 + c0;
            int b4 = boff & ~3;
            uint32_t lo = *(const uint32_t*)(sx + b4);
            if (boff & 2) {
                uint32_t hi = *(const uint32_t*)(sx + b4 + 4);
                V[r] = __funnelshift_r(lo, hi, 16);
            } else {
                V[r] = lo;
            }
        }
        uint32_t Q[4][2];
        #pragma unroll
        for (int r = 0; r < 4; r++) {
            Q[r][0] = V[r] & 0x00FFFFFFu;
            Q[r][1] = (V[r] >> 8) & 0x00FFFFFFu;
        }
        int8_t* arow = a1s + tid * A1S;
        #pragma unroll
        for (int g = 0; g < 8; g++) {
            uint32_t pk = 0;
            #pragma unroll
            for (int j = 0; j < 4; j++) {
                int oc = g * 4 + j;
                uint32_t w0 = swp[oc * 3 + 0], w1 = swp[oc * 3 + 1],
                         w2 = swp[oc * 3 + 2];
                int a00 = dp4(Q[0][0], w0, dp4(Q[1][0], w1, dp4(Q[2][0], w2, 0)));
                int a01 = dp4(Q[0][1], w0, dp4(Q[1][1], w1, dp4(Q[2][1], w2, 0)));
                int a10 = dp4(Q[1][0], w0, dp4(Q[2][0], w1, dp4(Q[3][0], w2, 0)));
                int a11 = dp4(Q[1][1], w0, dp4(Q[2][1], w1, dp4(Q[3][1], w2, 0)));
                int m = max(max(a00, a01), max(a10, a11));
                float v = (float)m * mul1;
                int q = clampi((int)rintf(v * inv_a1), 0, 15);
                float v2 = (float)q * s_a1;
                int q2 = clampi((int)rintf(v2 * inv_in), -8, 7);
                pk |= ((uint32_t)q2 & 0xFFu) << (j * 8);
            }
            *(uint32_t*)(arow + g * 4) = pk;
        }
    }
    CPW0();
    __syncthreads();

    // conv2 IMMA: A[128 conv-pix][288] gathered from a1s, B = sw2 [64 oc][288]
    int wm = wid >> 1, wn = wid & 1;
    int c[2][4][4];
    #pragma unroll
    for (int h = 0; h < 2; h++)
        #pragma unroll
        for (int nt = 0; nt < 4; nt++)
            #pragma unroll
            for (int e = 0; e < 4; e++) c[h][nt][e] = 0;

    uint32_t bbase = smem_u32(sw2)
                   + (wn * 32 + (lane & 7) + ((lane >> 4) << 3)) * WS2
                   + (((lane >> 3) & 1) << 4);
    uint32_t abase_h[2];
    {
        int khalf = lane >> 4;
        #pragma unroll
        for (int h = 0; h < 2; h++) {
            int p = h * 64 + wm * 16 + (lane & 15);
            int cy = p / 11, cx = p % 11;
            abase_h[h] = smem_u32(a1s) + (cy * 13 + cx) * A1S + khalf * 16;
        }
    }

    #pragma unroll
    for (int h = 0; h < 2; h++) {
        #pragma unroll
        for (int ks = 0; ks < 9; ks++) {
            int ky = ks / 3, kx = ks % 3;
            uint32_t a[4];
            ldsm4(a[0], a[1], a[2], a[3], abase_h[h] + (ky * 13 + kx) * A1S);
            uint32_t bb[4][2];
            #pragma unroll
            for (int j = 0; j < 2; j++) {
                uint32_t r0, r1, r2, r3;
                ldsm4(r0, r1, r2, r3, bbase + j * 16 * WS2 + ks * 32);
                bb[2 * j][0] = r0;     bb[2 * j][1] = r1;
                bb[2 * j + 1][0] = r2; bb[2 * j + 1][1] = r3;
            }
            #pragma unroll
            for (int nt = 0; nt < 4; nt++)
                imma16832(c[h][nt], a, bb[nt]);
        }
    }
    __syncthreads();   // done reading sw2/a1s -> reuse S as C

    int* Cs = (int*)S;  // [128 pix][68] int
    #pragma unroll
    for (int h = 0; h < 2; h++) {
        int row = h * 64 + wm * 16 + (lane >> 2);
        #pragma unroll
        for (int nt = 0; nt < 4; nt++) {
            int col = wn * 32 + nt * 8 + ((lane & 3) << 1);
            int2 v0 = make_int2(c[h][nt][0], c[h][nt][1]);
            int2 v1 = make_int2(c[h][nt][2], c[h][nt][3]);
            *(int2*)(Cs + row * 68 + col) = v0;
            *(int2*)(Cs + (row + 8) * 68 + col) = v1;
        }
    }
    __syncthreads();

    float mul2 = s_in * (g_maxabs[1] / 7.0f);
    for (int o = tid; o < 1600; o += 256) {
        int oc = o / 25, p = o - oc * 25;
        int py = p / 5, px = p - py * 5;
        int cp0 = (2 * py) * 11 + 2 * px;
        int m = Cs[cp0 * 68 + oc];
        m = max(m, Cs[(cp0 + 1) * 68 + oc]);
        m = max(m, Cs[(cp0 + 11) * 68 + oc]);
        m = max(m, Cs[(cp0 + 12) * 68 + oc]);
        float v = (float)m * mul2;
        int q = clampi((int)rintf(v * inv_a2), 0, 15);
        float v2 = (float)q * s_a2;
        int q2 = clampi((int)rintf(v2 * inv_in), -8, 7);
        g_act2[b * 1600 + o] = (int8_t)q2;
    }
}

// ---------------- fc1: s8 IMMA GEMM, 64x64 tiles, BK=64, 3-stage pipeline -----
// Grid (64, 16) = 1024 CTAs, 128 threads (4 warps 2x2), warp tile 32x32.
__global__ __launch_bounds__(128) void fc1_imma_k(const float* __restrict__ s_in_p,
                                                  const float* __restrict__ s_a3_p) {
    __shared__ __align__(16) int8_t sA[3][64 * 80];
    __shared__ __align__(16) int8_t sB[3][64 * 80];
    const int BUFB = 64 * 80;

    int tid = threadIdx.x, lane = tid & 31, wid = tid >> 5;
    int wm = wid >> 1, wn = wid & 1;
    int bm = blockIdx.y, bn = blockIdx.x;

    int lrow = tid >> 1, lseg2 = (tid & 1) << 1;  // 64 rows x 2 x 16B pairs
    const char* gA0 = (const char*)g_act2 + (size_t)(bm * 64 + lrow) * 1600 + lseg2 * 16;
    const char* gB0 = (const char*)g_qwl1 + (size_t)(bn * 64 + lrow) * 1600 + lseg2 * 16;
    uint32_t smA0 = smem_u32(&sA[0][0]) + lrow * 80 + lseg2 * 16;
    uint32_t smB0 = smem_u32(&sB[0][0]) + lrow * 80 + lseg2 * 16;

    int c[2][4][4];
    #pragma unroll
    for (int i = 0; i < 2; i++)
        #pragma unroll
        for (int j = 0; j < 4; j++)
            #pragma unroll
            for (int e = 0; e < 4; e++) c[i][j][e] = 0;

    // prologue: chunks 0 and 1 as separate groups
    #pragma unroll
    for (int p = 0; p < 2; p++) {
        uint32_t da = smA0 + p * BUFB, db = smB0 + p * BUFB;
        const char* ga = gA0 + p * 64;
        const char* gb = gB0 + p * 64;
        CPA16(da, ga);
        CPA16(da + 16, ga + 16);
        CPA16(db, gb);
        CPA16(db + 16, gb + 16);
        CPC();
    }

    uint32_t saL = smem_u32(&sA[0][0]) + (wm * 32 + (lane & 15)) * 80 + ((lane >> 4) << 4);
    uint32_t sbL = smem_u32(&sB[0][0])
                 + (wn * 32 + (lane & 7) + ((lane >> 4) << 3)) * 80
                 + (((lane >> 3) & 1) << 4);

    int buf = 0;
    for (int kt = 0; kt < 25; kt++) {
        if (kt < 24) { CPW1(); } else { CPW0(); }
        __syncthreads();
        if (kt + 2 < 25) {
            int nb = (buf + 2) % 3;
            const char* ga = gA0 + (kt + 2) * 64;
            const char* gb = gB0 + (kt + 2) * 64;
            uint32_t da = smA0 + nb * BUFB, db = smB0 + nb * BUFB;
            CPA16(da, ga);
            CPA16(da + 16, ga + 16);
            CPA16(db, gb);
            CPA16(db + 16, gb + 16);
            CPC();
        }
        uint32_t sa = saL + buf * BUFB;
        uint32_t sb = sbL + buf * BUFB;
        #pragma unroll
        for (int ks = 0; ks < 2; ks++) {
            uint32_t a[2][4], bb[4][2];
            #pragma unroll
            for (int mt = 0; mt < 2; mt++)
                ldsm4(a[mt][0], a[mt][1], a[mt][2], a[mt][3],
                      sa + mt * 16 * 80 + ks * 32);
            #pragma unroll
            for (int j = 0; j < 2; j++) {
                uint32_t r0, r1, r2, r3;
                ldsm4(r0, r1, r2, r3, sb + j * 16 * 80 + ks * 32);
                bb[2 * j][0] = r0;     bb[2 * j][1] = r1;
                bb[2 * j + 1][0] = r2; bb[2 * j + 1][1] = r3;
            }
            #pragma unroll
            for (int mt = 0; mt < 2; mt++)
                #pragma unroll
                for (int nt = 0; nt < 4; nt++)
                    imma16832(c[mt][nt], a[mt], bb[nt]);
        }
        buf = (buf + 1) % 3;
    }

    float s_in = *s_in_p, s_a3 = *s_a3_p;
    float mul = s_in * (g_maxabs[2] / 7.0f);
    float isa3 = 1.0f / s_a3;  // power of two -> exact
    int r0 = bm * 64 + wm * 32 + (lane >> 2);
    int c0 = bn * 64 + wn * 32 + ((lane & 3) << 1);
    #pragma unroll
    for (int mt = 0; mt < 2; mt++) {
        #pragma unroll
        for (int nt = 0; nt < 4; nt++) {
            int rr = r0 + mt * 16, cc = c0 + nt * 8;
            int* cf = c[mt][nt];
            uchar2 lo, hi;
            lo.x = (uint8_t)clampi((int)rintf((float)cf[0] * mul * isa3), 0, 15);
            lo.y = (uint8_t)clampi((int)rintf((float)cf[1] * mul * isa3), 0, 15);
            hi.x = (uint8_t)clampi((int)rintf((float)cf[2] * mul * isa3), 0, 15);
            hi.y = (uint8_t)clampi((int)rintf((float)cf[3] * mul * isa3), 0, 15);
            *(uchar2*)(g_act3 + rr * 4096 + cc) = lo;
            *(uchar2*)(g_act3 + (rr + 8) * 4096 + cc) = hi;
        }
    }
}

// ---------------- fc2: [1024,4096] x [10,4096]^T -> out (+ scale reset tail) ----
__global__ void fc2_k(const float* __restrict__ s_a3_p, float* __restrict__ out) {
    int b = blockIdx.x;
    int wj = threadIdx.x >> 5, lane = threadIdx.x & 31;
    const int* ar = (const int*)(g_act3 + b * 4096);
    const int* wr = (const int*)(g_qwl2 + wj * 4096);
    int acc = 0;
    for (int t = lane; t < 1024; t += 32)
        acc = __dp4a(ar[t], wr[t], acc);
    #pragma unroll
    for (int o = 16; o; o >>= 1) acc += __shfl_xor_sync(0xffffffffu, acc, o);
    if (lane == 0)
        out[b * 10 + wj] = (float)acc * (*s_a3_p) * (g_maxabs[3] / 7.0f);

    // last-finishing block resets scales for the next replay (deterministic)
    __syncthreads();
    if (threadIdx.x == 0) {
        __threadfence();
        if (atomicAdd(&g_cnt2, 1) == (int)gridDim.x - 1) {
            g_maxabs[0] = 0.0f; g_maxabs[1] = 0.0f;
            g_maxabs[2] = 0.0f; g_maxabs[3] = 0.0f;
            g_cnt2 = 0;
            __threadfence();
        }
    }
}

// ---------------- launcher ----------------
extern "C" void kernel_launch(void* const* d_in, const int* in_sizes, int n_in,
                              void* d_out, int out_size) {
    const float* x    = (const float*)d_in[0];
    const float* w1   = (const float*)d_in[1];
    const float* w2   = (const float*)d_in[2];
    const float* wl1  = (const float*)d_in[3];
    const float* wl2  = (const float*)d_in[4];
    const float* s_in = (const float*)d_in[5];
    const float* s_a1 = (const float*)d_in[6];
    const float* s_a2 = (const float*)d_in[7];
    const float* s_a3 = (const float*)d_in[8];
    float* out = (float*)d_out;

    prep1_k<<<1475, 256>>>(w1, w2, wl1, wl2, x, s_in);     // maxabs + quant_x
    quant_small_k<<<234, 256>>>(w1, w2, wl2);              // w1/w2/wl2 quant
    conv12_k<<<3072, 256>>>(s_in, s_a1, s_a2, wl1);        // conv + wl1 quant overlap
    fc1_imma_k<<<dim3(64, 16), 128>>>(s_in, s_a3);         // 4th launch -> ncu capture
    fc2_k<<<1024, 320>>>(s_a3, out);
}

// round 16
// speedup vs baseline: 3.1174x; 1.5102x over previous
#include <cuda_runtime.h>
#include <cuda_bf16.h>
#include <cuda_fp8.h>
#include <stdint.h>

#define NB 1024

// ---------------- scratch (no allocations allowed) ----------------
__device__ float g_maxabs[4];                           // zero-init; reset by fc2 tail
__device__ int   g_cnt2;                                // fc2 completion ticket
__device__ __align__(16) int8_t g_qx  [NB * 784];       // quantized input q
__device__ __align__(16) int8_t g_qw1 [32 * 9];         // [oc][kpos]
__device__ __align__(16) int8_t g_qw2 [64 * 9 * 32];    // [oc][kpos 9][ic 32] rows of 288
__device__ __align__(16) uint8_t g_act2[NB * 1600];     // fc1 A: q as e4m3 bytes
__device__ __align__(16) uint8_t g_qwl1[4096 * 1600];   // fc1 B: q as e4m3 bytes [n][k]
__device__ __align__(16) int8_t g_act3[NB * 4096];      // fc1 output q (0..15)
__device__ __align__(16) int8_t g_qwl2[10 * 4096];      // [n][k]

__device__ __forceinline__ int clampi(int v, int lo, int hi) {
    return max(lo, min(hi, v));
}
__device__ __forceinline__ int dp4(uint32_t a, uint32_t b, int c) {
    return __dp4a((int)a, (int)b, c);   // signed byte dot-product
}
__device__ __forceinline__ uint8_t to_e4m3(int q) {
    __nv_fp8_e4m3 e((float)q);          // integers |q|<=8 exact in e4m3
    return *(uint8_t*)&e;
}
__device__ __forceinline__ uint32_t smem_u32(const void* p) {
    return (uint32_t)__cvta_generic_to_shared(p);
}
__device__ __forceinline__ void ldsm4(uint32_t& r0, uint32_t& r1, uint32_t& r2,
                                      uint32_t& r3, uint32_t a) {
    asm volatile("ldmatrix.sync.aligned.m8n8.x4.shared.b16 {%0,%1,%2,%3}, [%4];\n"
                 : "=r"(r0), "=r"(r1), "=r"(r2), "=r"(r3) : "r"(a));
}
__device__ __forceinline__ void imma16832(int* c, const uint32_t* a, const uint32_t* b) {
    asm volatile(
        "mma.sync.aligned.m16n8k32.row.col.s32.s8.s8.s32 "
        "{%0,%1,%2,%3},{%4,%5,%6,%7},{%8,%9},{%0,%1,%2,%3};\n"
        : "+r"(c[0]), "+r"(c[1]), "+r"(c[2]), "+r"(c[3])
        : "r"(a[0]), "r"(a[1]), "r"(a[2]), "r"(a[3]), "r"(b[0]), "r"(b[1]));
}
// FP8 e4m3 MMA, f32 accumulators; fragment bytes identical to s8 k32 layout.
__device__ __forceinline__ void qmma16832(float* c, const uint32_t* a, const uint32_t* b) {
    asm volatile(
        "mma.sync.aligned.m16n8k32.row.col.f32.e4m3.e4m3.f32 "
        "{%0,%1,%2,%3},{%4,%5,%6,%7},{%8,%9},{%0,%1,%2,%3};\n"
        : "+f"(c[0]), "+f"(c[1]), "+f"(c[2]), "+f"(c[3])
        : "r"(a[0]), "r"(a[1]), "r"(a[2]), "r"(a[3]), "r"(b[0]), "r"(b[1]));
}
#define CPA16(dst, src) \
    asm volatile("cp.async.cg.shared.global [%0], [%1], 16;\n" ::"r"(dst), "l"(src))
#define CPC()  asm volatile("cp.async.commit_group;\n")
#define CPW0() asm volatile("cp.async.wait_group 0;\n")

// ---------------- maxabs (+ fused quant_x) ----------------
__device__ void maxabs_dev(const float* __restrict__ w, int n4, int idx,
                           int bid, int nblocks) {
    const float4* w4 = (const float4*)w;
    int G = nblocks * 256;
    int i0 = bid * 256 + threadIdx.x;
    float m0 = 0.f, m1 = 0.f, m2 = 0.f, m3 = 0.f;
    for (int i = i0; i < n4; i += 4 * G) {
        float4 v = w4[i];
        m0 = fmaxf(m0, fmaxf(fmaxf(fabsf(v.x), fabsf(v.y)),
                             fmaxf(fabsf(v.z), fabsf(v.w))));
        int i1 = i + G;
        if (i1 < n4) {
            float4 u = w4[i1];
            m1 = fmaxf(m1, fmaxf(fmaxf(fabsf(u.x), fabsf(u.y)),
                                 fmaxf(fabsf(u.z), fabsf(u.w))));
        }
        int i2 = i + 2 * G;
        if (i2 < n4) {
            float4 u = w4[i2];
            m2 = fmaxf(m2, fmaxf(fmaxf(fabsf(u.x), fabsf(u.y)),
                                 fmaxf(fabsf(u.z), fabsf(u.w))));
        }
        int i3 = i + 3 * G;
        if (i3 < n4) {
            float4 u = w4[i3];
            m3 = fmaxf(m3, fmaxf(fmaxf(fabsf(u.x), fabsf(u.y)),
                                 fmaxf(fabsf(u.z), fabsf(u.w))));
        }
    }
    float m = fmaxf(fmaxf(m0, m1), fmaxf(m2, m3));
    #pragma unroll
    for (int o = 16; o; o >>= 1) m = fmaxf(m, __shfl_xor_sync(0xffffffffu, m, o));
    __shared__ float sm[8];
    int lane = threadIdx.x & 31, wid = threadIdx.x >> 5;
    if (lane == 0) sm[wid] = m;
    __syncthreads();
    if (wid == 0) {
        m = (lane < 8) ? sm[lane] : 0.0f;
        #pragma unroll
        for (int o = 4; o; o >>= 1) m = fmaxf(m, __shfl_xor_sync(0xffffffffu, m, o));
        if (lane == 0) atomicMax((int*)&g_maxabs[idx], __float_as_int(m));
    }
}

// blocks: [0,1024) wl1 max, [1024,1042) w2, [1042,1082) wl2, [1082] w1,
//         [1083, 1475) quant_x (each thread covers 2 elements: i, i+100352)
__global__ void prep1_k(const float* __restrict__ w1,
                        const float* __restrict__ w2,
                        const float* __restrict__ wl1,
                        const float* __restrict__ wl2,
                        const float* __restrict__ x,
                        const float* __restrict__ s_in_p) {
    int bx = blockIdx.x;
    if (bx < 1024)        maxabs_dev(wl1, (4096 * 1600) >> 2, 2, bx, 1024);
    else if (bx < 1042)   maxabs_dev(w2, (64 * 32 * 9) >> 2, 1, bx - 1024, 18);
    else if (bx < 1082)   maxabs_dev(wl2, (10 * 4096) >> 2, 3, bx - 1042, 40);
    else if (bx == 1082)  maxabs_dev(w1, (32 * 9) >> 2, 0, 0, 1);
    else {
        float inv = 1.0f / *s_in_p;  // s_in power of two -> exact
        const int n4 = (NB * 784) >> 2;  // 200704
        const int half = 392 * 256;      // 100352
        const float4* x4 = (const float4*)x;
        char4* q4 = (char4*)g_qx;
        int i = (bx - 1083) * 256 + (int)threadIdx.x;
        #pragma unroll
        for (int rep = 0; rep < 2; rep++) {
            int ii = i + rep * half;
            if (ii < n4) {
                float4 v = x4[ii];
                char4 q;
                q.x = (char)clampi((int)rintf(v.x * inv), -8, 7);
                q.y = (char)clampi((int)rintf(v.y * inv), -8, 7);
                q.z = (char)clampi((int)rintf(v.z * inv), -8, 7);
                q.w = (char)clampi((int)rintf(v.w * inv), -8, 7);
                q4[ii] = q;
            }
        }
    }
}

// small weights only: blocks [0,160) wl2, [160,232) w2, [232,234) w1
__global__ void quant_small_k(const float* __restrict__ w1,
                              const float* __restrict__ w2,
                              const float* __restrict__ wl2) {
    int bx = blockIdx.x, tid = threadIdx.x;
    if (bx < 160) {
        float s = g_maxabs[3] / 7.0f;
        int i = bx * 256 + tid;
        if (i < 10 * 4096)
            g_qwl2[i] = (int8_t)clampi((int)rintf(wl2[i] / s), -7, 7);
    } else if (bx < 232) {
        float s = g_maxabs[1] / 7.0f;
        int i = (bx - 160) * 256 + tid;
        if (i < 64 * 9 * 32) {
            int oc = i / 288, r = i % 288;
            int pos = r >> 5, ic = r & 31;
            float v = w2[(oc * 32 + ic) * 9 + pos];
            g_qw2[i] = (int8_t)clampi((int)rintf(v / s), -7, 7);
        }
    } else {
        float s = g_maxabs[0] / 7.0f;
        int i = (bx - 232) * 256 + tid;
        if (i < 32 * 9)
            g_qw1[i] = (int8_t)clampi((int)rintf(w1[i] / s), -7, 7);
    }
}

// ---------------- fused conv1+pool+fq -> conv2(IMMA)+pool+fq  [+ wl1 quant] ----
// blocks [0,1024): conv path per image. blocks [1024,3072): wl1 e4m3 quantization.
#define A1S 48
#define WS2 304
__global__ __launch_bounds__(256) void conv12_k(const float* __restrict__ s_in_p,
                                                const float* __restrict__ s_a1_p,
                                                const float* __restrict__ s_a2_p,
                                                const float* __restrict__ wl1) {
    __shared__ __align__(16) int8_t S[35072];
    int b = blockIdx.x, tid = threadIdx.x;

    if (b >= 1024) {   // ---- wl1 quantization -> e4m3 bytes, overlapped ----
        float rinv = 1.0f / (g_maxabs[2] / 7.0f);
        const int n4 = (4096 * 1600) >> 2;
        const float4* w4 = (const float4*)wl1;
        uchar4* o4 = (uchar4*)g_qwl1;
        for (int i = (b - 1024) * 256 + tid; i < n4; i += 2048 * 256) {
            float4 v = w4[i];
            uchar4 q;
            q.x = to_e4m3(clampi((int)rintf(v.x * rinv), -7, 7));
            q.y = to_e4m3(clampi((int)rintf(v.y * rinv), -7, 7));
            q.z = to_e4m3(clampi((int)rintf(v.z * rinv), -7, 7));
            q.w = to_e4m3(clampi((int)rintf(v.w * rinv), -7, 7));
            o4[i] = q;
        }
        return;
    }

    int8_t* sw2 = S;                             // 64*304 = 19456
    int8_t* a1s = S + 19456;                     // act1 tile (stride 48), 8576
    int8_t* sx  = S + 28032;                     // 784
    uint32_t* swp = (uint32_t*)(S + 28832);      // packed conv1 weights, 96 u32
    int lane = tid & 31, wid = tid >> 5;

    for (int idx = tid; idx < 1152; idx += 256) {
        int row = idx / 18, seg = idx % 18;
        CPA16(smem_u32(sw2 + row * WS2 + seg * 16),
              (const char*)g_qw2 + row * 288 + seg * 16);
    }
    CPC();
    {
        const int* gx = (const int*)(g_qx + b * 784);
        int* sxi = (int*)sx;
        for (int i = tid; i < 196; i += 256) sxi[i] = gx[i];
        if (tid < 96) {  // pack w1[oc][ky][0..2] -> u32 with zero 4th byte
            int oc = tid / 3, ky = tid - oc * 3;
            const uint8_t* wp = (const uint8_t*)g_qw1 + oc * 9 + ky * 3;
            swp[tid] = (uint32_t)wp[0] | ((uint32_t)wp[1] << 8)
                     | ((uint32_t)wp[2] << 16);
        }
    }
    __syncthreads();

    float s_in = *s_in_p, s_a1 = *s_a1_p, s_a2 = *s_a2_p;
    float inv_in = 1.0f / s_in, inv_a1 = 1.0f / s_a1, inv_a2 = 1.0f / s_a2;
    float mul1 = s_in * (g_maxabs[0] / 7.0f);

    if (tid < 169) {
        int py = tid / 13, px = tid - py * 13;
        int c0 = 2 * px;
        uint32_t V[4];
        #pragma unroll
        for (int r = 0; r < 4; r++) {
            int boff = (2 * py + r) * 28 + c0;
            int b4 = boff & ~3;
            uint32_t lo = *(const uint32_t*)(sx + b4);
            if (boff & 2) {
                uint32_t hi = *(const uint32_t*)(sx + b4 + 4);
                V[r] = __funnelshift_r(lo, hi, 16);
            } else {
                V[r] = lo;
            }
        }
        uint32_t Q[4][2];
        #pragma unroll
        for (int r = 0; r < 4; r++) {
            Q[r][0] = V[r] & 0x00FFFFFFu;
            Q[r][1] = (V[r] >> 8) & 0x00FFFFFFu;
        }
        int8_t* arow = a1s + tid * A1S;
        #pragma unroll
        for (int g = 0; g < 8; g++) {
            uint32_t pk = 0;
            #pragma unroll
            for (int j = 0; j < 4; j++) {
                int oc = g * 4 + j;
                uint32_t w0 = swp[oc * 3 + 0], w1 = swp[oc * 3 + 1],
                         w2 = swp[oc * 3 + 2];
                int a00 = dp4(Q[0][0], w0, dp4(Q[1][0], w1, dp4(Q[2][0], w2, 0)));
                int a01 = dp4(Q[0][1], w0, dp4(Q[1][1], w1, dp4(Q[2][1], w2, 0)));
                int a10 = dp4(Q[1][0], w0, dp4(Q[2][0], w1, dp4(Q[3][0], w2, 0)));
                int a11 = dp4(Q[1][1], w0, dp4(Q[2][1], w1, dp4(Q[3][1], w2, 0)));
                int m = max(max(a00, a01), max(a10, a11));
                float v = (float)m * mul1;
                int q = clampi((int)rintf(v * inv_a1), 0, 15);
                float v2 = (float)q * s_a1;
                int q2 = clampi((int)rintf(v2 * inv_in), -8, 7);
                pk |= ((uint32_t)q2 & 0xFFu) << (j * 8);
            }
            *(uint32_t*)(arow + g * 4) = pk;
        }
    }
    CPW0();
    __syncthreads();

    // conv2 IMMA: A[128 conv-pix][288] gathered from a1s, B = sw2 [64 oc][288]
    int wm = wid >> 1, wn = wid & 1;
    int c[2][4][4];
    #pragma unroll
    for (int h = 0; h < 2; h++)
        #pragma unroll
        for (int nt = 0; nt < 4; nt++)
            #pragma unroll
            for (int e = 0; e < 4; e++) c[h][nt][e] = 0;

    uint32_t bbase = smem_u32(sw2)
                   + (wn * 32 + (lane & 7) + ((lane >> 4) << 3)) * WS2
                   + (((lane >> 3) & 1) << 4);
    uint32_t abase_h[2];
    {
        int khalf = lane >> 4;
        #pragma unroll
        for (int h = 0; h < 2; h++) {
            int p = h * 64 + wm * 16 + (lane & 15);
            int cy = p / 11, cx = p % 11;
            abase_h[h] = smem_u32(a1s) + (cy * 13 + cx) * A1S + khalf * 16;
        }
    }

    #pragma unroll
    for (int h = 0; h < 2; h++) {
        #pragma unroll
        for (int ks = 0; ks < 9; ks++) {
            int ky = ks / 3, kx = ks % 3;
            uint32_t a[4];
            ldsm4(a[0], a[1], a[2], a[3], abase_h[h] + (ky * 13 + kx) * A1S);
            uint32_t bb[4][2];
            #pragma unroll
            for (int j = 0; j < 2; j++) {
                uint32_t r0, r1, r2, r3;
                ldsm4(r0, r1, r2, r3, bbase + j * 16 * WS2 + ks * 32);
                bb[2 * j][0] = r0;     bb[2 * j][1] = r1;
                bb[2 * j + 1][0] = r2; bb[2 * j + 1][1] = r3;
            }
            #pragma unroll
            for (int nt = 0; nt < 4; nt++)
                imma16832(c[h][nt], a, bb[nt]);
        }
    }
    __syncthreads();   // done reading sw2/a1s -> reuse S as C

    int* Cs = (int*)S;  // [128 pix][68] int
    #pragma unroll
    for (int h = 0; h < 2; h++) {
        int row = h * 64 + wm * 16 + (lane >> 2);
        #pragma unroll
        for (int nt = 0; nt < 4; nt++) {
            int col = wn * 32 + nt * 8 + ((lane & 3) << 1);
            int2 v0 = make_int2(c[h][nt][0], c[h][nt][1]);
            int2 v1 = make_int2(c[h][nt][2], c[h][nt][3]);
            *(int2*)(Cs + row * 68 + col) = v0;
            *(int2*)(Cs + (row + 8) * 68 + col) = v1;
        }
    }
    __syncthreads();

    float mul2 = s_in * (g_maxabs[1] / 7.0f);
    for (int o = tid; o < 1600; o += 256) {
        int oc = o / 25, p = o - oc * 25;
        int py = p / 5, px = p - py * 5;
        int cp0 = (2 * py) * 11 + 2 * px;
        int m = Cs[cp0 * 68 + oc];
        m = max(m, Cs[(cp0 + 1) * 68 + oc]);
        m = max(m, Cs[(cp0 + 11) * 68 + oc]);
        m = max(m, Cs[(cp0 + 12) * 68 + oc]);
        float v = (float)m * mul2;
        int q = clampi((int)rintf(v * inv_a2), 0, 15);
        float v2 = (float)q * s_a2;
        int q2 = clampi((int)rintf(v2 * inv_in), -8, 7);
        g_act2[b * 1600 + o] = to_e4m3(q2);
    }
}

// ---------------- fc1: e4m3 FP8 MMA GEMM, 64x64 tiles, BK=64, 2-stage ---------
// Grid (64, 16) = 1024 CTAs, 128 threads (4 warps 2x2), warp tile 32x32.
__global__ __launch_bounds__(128) void fc1_mma_k(const float* __restrict__ s_in_p,
                                                 const float* __restrict__ s_a3_p) {
    __shared__ __align__(16) uint8_t sA[2][64 * 80];
    __shared__ __align__(16) uint8_t sB[2][64 * 80];
    const int BUFB = 64 * 80;

    int tid = threadIdx.x, lane = tid & 31, wid = tid >> 5;
    int wm = wid >> 1, wn = wid & 1;
    int bm = blockIdx.y, bn = blockIdx.x;

    int lrow = tid >> 1, lseg2 = (tid & 1) << 1;
    const char* gA0 = (const char*)g_act2 + (size_t)(bm * 64 + lrow) * 1600 + lseg2 * 16;
    const char* gB0 = (const char*)g_qwl1 + (size_t)(bn * 64 + lrow) * 1600 + lseg2 * 16;
    uint32_t smA0 = smem_u32(&sA[0][0]) + lrow * 80 + lseg2 * 16;
    uint32_t smB0 = smem_u32(&sB[0][0]) + lrow * 80 + lseg2 * 16;

    float c[2][4][4];
    #pragma unroll
    for (int i = 0; i < 2; i++)
        #pragma unroll
        for (int j = 0; j < 4; j++)
            #pragma unroll
            for (int e = 0; e < 4; e++) c[i][j][e] = 0.0f;

    CPA16(smA0, gA0);
    CPA16(smA0 + 16, gA0 + 16);
    CPA16(smB0, gB0);
    CPA16(smB0 + 16, gB0 + 16);
    CPC(); CPW0();
    __syncthreads();

    uint32_t saL = smem_u32(&sA[0][0]) + (wm * 32 + (lane & 15)) * 80 + ((lane >> 4) << 4);
    uint32_t sbL = smem_u32(&sB[0][0])
                 + (wn * 32 + (lane & 7) + ((lane >> 4) << 3)) * 80
                 + (((lane >> 3) & 1) << 4);

    int buf = 0;
    for (int kt = 0; kt < 25; kt++) {
        if (kt < 24) {
            int nb = buf ^ 1;
            const char* ga = gA0 + (kt + 1) * 64;
            const char* gb = gB0 + (kt + 1) * 64;
            uint32_t da = smA0 + nb * BUFB, db = smB0 + nb * BUFB;
            CPA16(da, ga);
            CPA16(da + 16, ga + 16);
            CPA16(db, gb);
            CPA16(db + 16, gb + 16);
            CPC();
        }
        uint32_t sa = saL + buf * BUFB;
        uint32_t sb = sbL + buf * BUFB;
        #pragma unroll
        for (int ks = 0; ks < 2; ks++) {
            uint32_t a[2][4], bb[4][2];
            #pragma unroll
            for (int mt = 0; mt < 2; mt++)
                ldsm4(a[mt][0], a[mt][1], a[mt][2], a[mt][3],
                      sa + mt * 16 * 80 + ks * 32);
            #pragma unroll
            for (int j = 0; j < 2; j++) {
                uint32_t r0, r1, r2, r3;
                ldsm4(r0, r1, r2, r3, sb + j * 16 * 80 + ks * 32);
                bb[2 * j][0] = r0;     bb[2 * j][1] = r1;
                bb[2 * j + 1][0] = r2; bb[2 * j + 1][1] = r3;
            }
            #pragma unroll
            for (int mt = 0; mt < 2; mt++)
                #pragma unroll
                for (int nt = 0; nt < 4; nt++)
                    qmma16832(c[mt][nt], a[mt], bb[nt]);
        }
        if (kt < 24) {
            CPW0();
            __syncthreads();
            buf ^= 1;
        }
    }

    float s_in = *s_in_p, s_a3 = *s_a3_p;
    float mul = s_in * (g_maxabs[2] / 7.0f);
    float isa3 = 1.0f / s_a3;  // power of two -> exact
    int r0 = bm * 64 + wm * 32 + (lane >> 2);
    int c0 = bn * 64 + wn * 32 + ((lane & 3) << 1);
    #pragma unroll
    for (int mt = 0; mt < 2; mt++) {
        #pragma unroll
        for (int nt = 0; nt < 4; nt++) {
            int rr = r0 + mt * 16, cc = c0 + nt * 8;
            float* cf = c[mt][nt];
            uchar2 lo, hi;
            lo.x = (uint8_t)clampi((int)rintf(cf[0] * mul * isa3), 0, 15);
            lo.y = (uint8_t)clampi((int)rintf(cf[1] * mul * isa3), 0, 15);
            hi.x = (uint8_t)clampi((int)rintf(cf[2] * mul * isa3), 0, 15);
            hi.y = (uint8_t)clampi((int)rintf(cf[3] * mul * isa3), 0, 15);
            *(uchar2*)(g_act3 + rr * 4096 + cc) = lo;
            *(uchar2*)(g_act3 + (rr + 8) * 4096 + cc) = hi;
        }
    }
}

// ---------------- fc2: [1024,4096] x [10,4096]^T -> out (+ scale reset tail) ----
__global__ void fc2_k(const float* __restrict__ s_a3_p, float* __restrict__ out) {
    int b = blockIdx.x;
    int wj = threadIdx.x >> 5, lane = threadIdx.x & 31;
    const int* ar = (const int*)(g_act3 + b * 4096);
    const int* wr = (const int*)(g_qwl2 + wj * 4096);
    int acc = 0;
    for (int t = lane; t < 1024; t += 32)
        acc = __dp4a(ar[t], wr[t], acc);
    #pragma unroll
    for (int o = 16; o; o >>= 1) acc += __shfl_xor_sync(0xffffffffu, acc, o);
    if (lane == 0)
        out[b * 10 + wj] = (float)acc * (*s_a3_p) * (g_maxabs[3] / 7.0f);

    // last-finishing block resets scales for the next replay (deterministic)
    __syncthreads();
    if (threadIdx.x == 0) {
        __threadfence();
        if (atomicAdd(&g_cnt2, 1) == (int)gridDim.x - 1) {
            g_maxabs[0] = 0.0f; g_maxabs[1] = 0.0f;
            g_maxabs[2] = 0.0f; g_maxabs[3] = 0.0f;
            g_cnt2 = 0;
            __threadfence();
        }
    }
}

// ---------------- launcher ----------------
extern "C" void kernel_launch(void* const* d_in, const int* in_sizes, int n_in,
                              void* d_out, int out_size) {
    const float* x    = (const float*)d_in[0];
    const float* w1   = (const float*)d_in[1];
    const float* w2   = (const float*)d_in[2];
    const float* wl1  = (const float*)d_in[3];
    const float* wl2  = (const float*)d_in[4];
    const float* s_in = (const float*)d_in[5];
    const float* s_a1 = (const float*)d_in[6];
    const float* s_a2 = (const float*)d_in[7];
    const float* s_a3 = (const float*)d_in[8];
    float* out = (float*)d_out;

    prep1_k<<<1475, 256>>>(w1, w2, wl1, wl2, x, s_in);     // maxabs + quant_x
    quant_small_k<<<234, 256>>>(w1, w2, wl2);              // w1/w2/wl2 quant
    conv12_k<<<3072, 256>>>(s_in, s_a1, s_a2, wl1);        // conv + wl1 quant overlap
    fc1_mma_k<<<dim3(64, 16), 128>>>(s_in, s_a3);          // 4th launch -> ncu capture
    fc2_k<<<1024, 320>>>(s_a3, out);
}